// round 7
// baseline (speedup 1.0000x reference)
#include <cuda_runtime.h>
#include <cuda_pipeline.h>
#include <cstdint>

// CTC batch cost, forward (loss only). B=128, T=1024, C=256 (blank=255),
// Lmax=64, S=129.
//
//  - one warp (one CTA) per batch element; 5 states/thread (160 >= 129, masked)
//  - probability-domain recurrence, per-thread block-floating-point scales,
//    frontier-safe scan renorm for first 16 chunks (R5 numerics, rel_err 1.5e-6)
//  - THIS ROUND: K=2 TIME-STEP FUSION. One halo exchange (6 parallel shfls)
//    covers two recurrence steps: each thread computes step-t results for its
//    5 states plus 2 halo states below, then step-t+1 fully locally. Serial
//    shfl latency per step is halved. cp.async issues interleaved between
//    fused steps (MIO burst relief).

#define T_DIM   1024
#define C_DIM   256
#define LMAX    64
#define PSTATES 5
#define NSTAGE  32
#define CHUNK   8
#define NCHUNK  (T_DIM / CHUNK)
#define SCANCH  16          // chunks using the frontier-safe scan renorm
#define EPSF    1e-7f
#define MFLOOR  1e-37f

__global__ __launch_bounds__(32, 1)
void ctc_loss_kernel(const int*   __restrict__ y_true,   // [B, LMAX]
                     const float* __restrict__ y_pred,   // [B, T, C]
                     const int*   __restrict__ in_len,   // [B, 1]
                     const int*   __restrict__ lab_len,  // [B, 1]
                     float*       __restrict__ out)      // [B, 1]
{
    __shared__ __align__(16) float stage[NSTAGE * C_DIM];
    __shared__ float fin_a [32 * PSTATES];
    __shared__ float fin_lc[32];

    const int b   = blockIdx.x;
    const int tid = threadIdx.x;
    const float* __restrict__ base = y_pred + (size_t)b * T_DIM * C_DIM;
    const int L    = lab_len[b];
    const int Tlen = in_len[b];
    const int Smax = 2 * L + 1;
    const int* __restrict__ yb = y_true + b * LMAX;

    // ---- per-state constants ----
    int   cls[PSTATES];
    float vm [PSTATES];
    float evm[PSTATES];
    float m2 [PSTATES];   // skip: s odd, s>=3, label != prev label
    #pragma unroll
    for (int j = 0; j < PSTATES; j++) {
        int s   = tid * PSTATES + j;
        int odd = s & 1;
        int li  = (s - 1) >> 1;
        int c   = (odd && li >= 0 && li < LMAX) ? yb[li] : (C_DIM - 1);
        bool valid = (s < Smax);
        cls[j] = c;
        vm [j] = valid ? 1.0f : 0.0f;
        evm[j] = valid ? EPSF : 0.0f;
        bool skip = odd && (s >= 3) && (li < LMAX) && (yb[li] != yb[li - 1]);
        m2 [j] = skip ? 1.0f : 0.0f;
    }
    // halo-state masks (state s-1, s-2 = neighbor's states 4, 3)
    const float mm1 = __shfl_up_sync(0xffffffffu, m2[PSTATES - 1], 1);
    const float mm2 = __shfl_up_sync(0xffffffffu, m2[PSTATES - 2], 1);

    // ---- async copy of one emission row (1 KB); always commits one group ----
    auto issue = [&](int t) {
        if (t < T_DIM) {
            const float4* src = (const float4*)(base + (size_t)t * C_DIM);
            float4*       dst = (float4*)&stage[(t & (NSTAGE - 1)) * C_DIM];
            __pipeline_memcpy_async(&dst[tid],      &src[tid],      16);
            __pipeline_memcpy_async(&dst[tid + 32], &src[tid + 32], 16);
        }
        __pipeline_commit();
    };

    float a[PSTATES];
    float logacc = 0.0f;                       // log sigma_i (per-thread scale)
    float rho    = (tid == 0) ? 0.0f : 1.0f;   // lane0 rho=0 replaces m1 mask

    // preload one chunk of emission probs (masked, eps-folded) into registers
    auto load_pv = [&](int t0, float (&pv)[CHUNK][PSTATES]) {
        #pragma unroll
        for (int i = 0; i < CHUNK; i++) {
            int t = t0 + i;
            if (t > T_DIM - 1) t = T_DIM - 1;
            const float* __restrict__ row = &stage[(t & (NSTAGE - 1)) * C_DIM];
            #pragma unroll
            for (int j = 0; j < PSTATES; j++)
                pv[i][j] = fmaf(row[cls[j]], vm[j], evm[j]);
        }
    };

    // single legacy step (used at t=1 and odd Tlen boundary)
    auto step1 = [&](int t, const float (&p)[PSTATES]) {
        if (t < Tlen) {
            float h1 = __shfl_up_sync(0xffffffffu, a[4], 1) * rho;
            float h2 = __shfl_up_sync(0xffffffffu, a[3], 1) * rho;
            float n0 = fmaf(h2,   m2[0], a[0] + h1)   * p[0];
            float n1 = fmaf(h1,   m2[1], a[1] + a[0]) * p[1];
            float n2 = fmaf(a[0], m2[2], a[2] + a[1]) * p[2];
            float n3 = fmaf(a[1], m2[3], a[3] + a[2]) * p[3];
            float n4 = fmaf(a[2], m2[4], a[4] + a[3]) * p[4];
            a[0] = n0; a[1] = n1; a[2] = n2; a[3] = n3; a[4] = n4;
        }
    };

    // fused 2 steps: one halo exchange covers t and t+1
    auto fused2 = [&](int t, const float (&p)[PSTATES], const float (&q)[PSTATES]) {
        if (t + 1 < Tlen) {
            float h1  = __shfl_up_sync(0xffffffffu, a[4], 1);
            float h2  = __shfl_up_sync(0xffffffffu, a[3], 1);
            float h3  = __shfl_up_sync(0xffffffffu, a[2], 1);
            float h4  = __shfl_up_sync(0xffffffffu, a[1], 1);
            float hp1 = __shfl_up_sync(0xffffffffu, p[4], 1);   // p_t[s-1]
            float hp2 = __shfl_up_sync(0xffffffffu, p[3], 1);   // p_t[s-2]
            h1 *= rho; h2 *= rho; h3 *= rho; h4 *= rho;         // lane0 -> 0
            // step t: b for local states plus 2 halo states below
            float bm2 = fmaf(h4,   mm2,   h2   + h3)   * hp2;
            float bm1 = fmaf(h3,   mm1,   h1   + h2)   * hp1;
            float b0  = fmaf(h2,   m2[0], a[0] + h1)   * p[0];
            float b1  = fmaf(h1,   m2[1], a[1] + a[0]) * p[1];
            float b2  = fmaf(a[0], m2[2], a[2] + a[1]) * p[2];
            float b3  = fmaf(a[1], m2[3], a[3] + a[2]) * p[3];
            float b4  = fmaf(a[2], m2[4], a[4] + a[3]) * p[4];
            // step t+1: fully local
            a[0] = fmaf(bm2, m2[0], b0 + bm1) * q[0];
            a[1] = fmaf(bm1, m2[1], b1 + b0 ) * q[1];
            a[2] = fmaf(b0,  m2[2], b2 + b1 ) * q[2];
            a[3] = fmaf(b1,  m2[3], b3 + b2 ) * q[3];
            a[4] = fmaf(b2,  m2[4], b4 + b3 ) * q[4];
        } else {
            step1(t, p);   // covers t==Tlen-1 (odd tail); no-op if t>=Tlen
        }
    };

    auto apply_scale = [&](float v) {
        float mprev = __shfl_up_sync(0xffffffffu, v, 1);   // lane0: own v
        float rinv  = __fdividef(1.0f, v);
        logacc += __logf(v);
        rho = fminf(rho * (mprev * rinv), 1e30f);          // lane0 stays 0
        #pragma unroll
        for (int j = 0; j < PSTATES; j++) a[j] *= rinv;
    };

    auto renorm_scan = [&]() {
        float lm = fmaxf(fmaxf(fmaxf(a[0], a[1]), fmaxf(a[2], a[3])), a[4]);
        float v  = lm;
        #pragma unroll
        for (int d = 1; d < 32; d <<= 1) {
            float up = __shfl_up_sync(0xffffffffu, v, d);
            v = (v > 0.0f) ? v : up;
        }
        v = fmaxf(v, MFLOOR);
        apply_scale(v);
    };

    auto renorm_fast = [&]() {
        float lm = fmaxf(fmaxf(fmaxf(a[0], a[1]), fmaxf(a[2], a[3])), a[4]);
        apply_scale(fmaxf(lm, MFLOOR));
    };

    float pvA[CHUNK][PSTATES];
    float pvB[CHUNK][PSTATES];

    // steady-state chunk body: steps on pcur, preload pnext, interleaved issues
    auto run_chunk = [&](int t0, const float (&pcur)[CHUNK][PSTATES],
                         float (&pnext)[CHUNK][PSTATES], bool scan) {
        __pipeline_wait_prior(CHUNK);
        __syncwarp();
        load_pv(t0 + CHUNK, pnext);
        #pragma unroll
        for (int i = 0; i < CHUNK; i += 2) {
            fused2(t0 + i, pcur[i], pcur[i + 1]);
            issue(t0 + 3 * CHUNK + i);
            issue(t0 + 3 * CHUNK + i + 1);
        }
        if (scan) renorm_scan(); else renorm_fast();
    };

    // ---- prologue: 24 rows in flight; preload chunk 0 ----
    for (int k = 0; k < 3 * CHUNK; k++) issue(k);
    __pipeline_wait_prior(2 * CHUNK);      // rows 0..7 complete
    __syncwarp();
    load_pv(0, pvA);

    // ---- chunk 0: init at t=0, step 1, fused 2/4/6 ----
    __pipeline_wait_prior(CHUNK);          // rows 8..15 complete
    __syncwarp();
    load_pv(CHUNK, pvB);
    #pragma unroll
    for (int j = 0; j < PSTATES; j++) {
        int s = tid * PSTATES + j;
        a[j]  = (s < 2) ? pvA[0][j] : 0.0f;
    }
    step1(1, pvA[1]);
    fused2(2, pvA[2], pvA[3]);
    fused2(4, pvA[4], pvA[5]);
    fused2(6, pvA[6], pvA[7]);
    renorm_scan();
    #pragma unroll
    for (int k = 0; k < CHUNK; k++) issue(3 * CHUNK + k);

    // ---- chunks 1..127 ----
    for (int c = 1; c < NCHUNK; c++) {
        bool scan = (c < SCANCH);
        if (c & 1) run_chunk(c * CHUNK, pvB, pvA, scan);
        else       run_chunk(c * CHUNK, pvA, pvB, scan);
    }

    // ---- finalize: ll = logaddexp over the two end states ----
    __syncwarp();
    #pragma unroll
    for (int j = 0; j < PSTATES; j++) fin_a[tid * PSTATES + j] = a[j];
    fin_lc[tid] = logacc;
    __syncwarp();
    if (tid == 0) {
        int  sa = 2 * L;
        int  sb = 2 * L - 1;                  // L >= 1 per setup
        float xa = __logf(fmaxf(fin_a[sa], MFLOOR)) + fin_lc[sa / PSTATES];
        float xb = __logf(fmaxf(fin_a[sb], MFLOOR)) + fin_lc[sb / PSTATES];
        float mxx = fmaxf(xa, xb);
        float mnn = fminf(xa, xb);
        float ll  = mxx + __logf(1.0f + __expf(mnn - mxx));
        out[b] = -ll;
    }
}

extern "C" void kernel_launch(void* const* d_in, const int* in_sizes, int n_in,
                              void* d_out, int out_size) {
    const int*   y_true  = (const int*)  d_in[0];   // [B,64] int32
    const float* y_pred  = (const float*)d_in[1];   // [B,1024,256] fp32
    const int*   in_len  = (const int*)  d_in[2];   // [B,1] int32
    const int*   lab_len = (const int*)  d_in[3];   // [B,1] int32
    float*       out     = (float*)      d_out;     // [B,1] fp32

    const int B = out_size;                          // 128
    ctc_loss_kernel<<<B, 32>>>(y_true, y_pred, in_len, lab_len, out);
}

// round 8
// speedup vs baseline: 1.0882x; 1.0882x over previous
#include <cuda_runtime.h>
#include <cuda_pipeline.h>
#include <cstdint>

// CTC batch cost, forward (loss only). B=128, T=1024, C=256 (blank=255),
// Lmax=64, S=129.
//
//  - one warp (one CTA) per batch element; 5 states/thread (160 >= 129, masked)
//  - probability-domain recurrence, per-thread block-floating-point scales,
//    frontier-safe scan renorm for first 16 chunks (R5 numerics, 1.5e-6)
//  - THIS ROUND: DEEP STREAMING RING. Rounds 5-7 ran at exactly
//    in_flight/latency per Little's law (~12KB in flight -> 1.9TB/s chip-wide).
//    Ring: 32 -> 128 rows (128KB dynamic smem), prefetch 14 chunks =
//    112KB in flight per CTA; one cp.async commit group per 8-row chunk;
//    refill issued immediately after the wait, before compute.

#define T_DIM   1024
#define C_DIM   256
#define LMAX    64
#define PSTATES 5
#define CHUNK   8
#define RINGC   16                      // ring capacity in chunks (128 rows)
#define NCHUNK  (T_DIM / CHUNK)         // 128
#define SCANCH  16                      // chunks using frontier-safe scan renorm
#define EPSF    1e-7f
#define MFLOOR  1e-37f
#define RING_BYTES (RINGC * CHUNK * C_DIM * 4)   // 131072

__global__ __launch_bounds__(32, 1)
void ctc_loss_kernel(const int*   __restrict__ y_true,   // [B, LMAX]
                     const float* __restrict__ y_pred,   // [B, T, C]
                     const int*   __restrict__ in_len,   // [B, 1]
                     const int*   __restrict__ lab_len,  // [B, 1]
                     float*       __restrict__ out)      // [B, 1]
{
    extern __shared__ __align__(16) float stage[];   // RINGC*CHUNK rows of C_DIM
    __shared__ float fin_a [32 * PSTATES];
    __shared__ float fin_lc[32];

    const int b   = blockIdx.x;
    const int tid = threadIdx.x;
    const float* __restrict__ base = y_pred + (size_t)b * T_DIM * C_DIM;
    const int L    = lab_len[b];
    const int Tlen = in_len[b];
    const int Smax = 2 * L + 1;
    const int* __restrict__ yb = y_true + b * LMAX;

    // ---- per-state constants ----
    int   cls[PSTATES];
    float vm [PSTATES];
    float evm[PSTATES];
    float m2 [PSTATES];
    #pragma unroll
    for (int j = 0; j < PSTATES; j++) {
        int s   = tid * PSTATES + j;
        int odd = s & 1;
        int li  = (s - 1) >> 1;
        int c   = (odd && li >= 0 && li < LMAX) ? yb[li] : (C_DIM - 1);
        bool valid = (s < Smax);
        cls[j] = c;
        vm [j] = valid ? 1.0f : 0.0f;
        evm[j] = valid ? EPSF : 0.0f;
        bool skip = odd && (s >= 3) && (li < LMAX) && (yb[li] != yb[li - 1]);
        m2 [j] = skip ? 1.0f : 0.0f;
    }

    // ---- one chunk (8 rows, 8KB) -> ring slot; single commit group ----
    auto issue_chunk = [&](int c) {
        const int base_row = (c & (RINGC - 1)) * CHUNK;
        #pragma unroll
        for (int i = 0; i < CHUNK; i++) {
            int t = c * CHUNK + i;
            if (t < T_DIM) {
                const float4* src = (const float4*)(base + (size_t)t * C_DIM);
                float4*       dst = (float4*)&stage[(base_row + i) * C_DIM];
                __pipeline_memcpy_async(&dst[tid],      &src[tid],      16);
                __pipeline_memcpy_async(&dst[tid + 32], &src[tid + 32], 16);
            }
        }
        __pipeline_commit();                 // always: keeps group count uniform
    };

    float a[PSTATES];
    float logacc = 0.0f;                       // log sigma_i (per-thread scale)
    float rho    = (tid == 0) ? 0.0f : 1.0f;   // lane0 rho=0 == m1 mask

    // one recurrence step; direct shared gather (R5-style)
    auto step1 = [&](int t, const float* __restrict__ row) {
        if (t < Tlen) {
            float h1 = __shfl_up_sync(0xffffffffu, a[4], 1) * rho;
            float h2 = __shfl_up_sync(0xffffffffu, a[3], 1) * rho;
            float p0 = fmaf(row[cls[0]], vm[0], evm[0]);
            float p1 = fmaf(row[cls[1]], vm[1], evm[1]);
            float p2 = fmaf(row[cls[2]], vm[2], evm[2]);
            float p3 = fmaf(row[cls[3]], vm[3], evm[3]);
            float p4 = fmaf(row[cls[4]], vm[4], evm[4]);
            float n0 = fmaf(h2,   m2[0], a[0] + h1)   * p0;
            float n1 = fmaf(h1,   m2[1], a[1] + a[0]) * p1;
            float n2 = fmaf(a[0], m2[2], a[2] + a[1]) * p2;
            float n3 = fmaf(a[1], m2[3], a[3] + a[2]) * p3;
            float n4 = fmaf(a[2], m2[4], a[4] + a[3]) * p4;
            a[0] = n0; a[1] = n1; a[2] = n2; a[3] = n3; a[4] = n4;
        }
    };

    auto apply_scale = [&](float v) {
        float mprev = __shfl_up_sync(0xffffffffu, v, 1);   // lane0: own v
        float rinv  = __fdividef(1.0f, v);
        logacc += __logf(v);
        rho = fminf(rho * (mprev * rinv), 1e30f);          // lane0 stays 0
        #pragma unroll
        for (int j = 0; j < PSTATES; j++) a[j] *= rinv;
    };

    auto renorm_scan = [&]() {       // frontier-safe: adopt nearest active below
        float lm = fmaxf(fmaxf(fmaxf(a[0], a[1]), fmaxf(a[2], a[3])), a[4]);
        float v  = lm;
        #pragma unroll
        for (int d = 1; d < 32; d <<= 1) {
            float up = __shfl_up_sync(0xffffffffu, v, d);
            v = (v > 0.0f) ? v : up;
        }
        v = fmaxf(v, MFLOOR);
        apply_scale(v);
    };

    auto renorm_fast = [&]() {
        float lm = fmaxf(fmaxf(fmaxf(a[0], a[1]), fmaxf(a[2], a[3])), a[4]);
        apply_scale(fmaxf(lm, MFLOOR));
    };

    // ---- prologue: fill ring with chunks 0..RINGC-2 (15 chunks, 120KB) ----
    for (int c = 0; c < RINGC - 1; c++) issue_chunk(c);

    // ---- chunk 0 ----
    __pipeline_wait_prior(RINGC - 2);   // chunk 0 complete; 14 chunks in flight
    __syncwarp();
    issue_chunk(RINGC - 1);             // top up immediately
    {
        const float* __restrict__ row0 = &stage[0];
        #pragma unroll
        for (int j = 0; j < PSTATES; j++) {
            int s   = tid * PSTATES + j;
            float p = fmaf(row0[cls[j]], vm[j], evm[j]);
            a[j]    = (s < 2) ? p : 0.0f;
        }
        #pragma unroll
        for (int i = 1; i < CHUNK; i++) step1(i, &stage[i * C_DIM]);
    }
    renorm_scan();

    // ---- chunks 1..NCHUNK-1 ----
    for (int c = 1; c < NCHUNK; c++) {
        __pipeline_wait_prior(RINGC - 2);   // chunk c resident
        __syncwarp();
        issue_chunk(c + RINGC - 1);         // refill before compute
        const int base_row = (c & (RINGC - 1)) * CHUNK;
        const int t0 = c * CHUNK;
        #pragma unroll
        for (int i = 0; i < CHUNK; i++)
            step1(t0 + i, &stage[(base_row + i) * C_DIM]);
        if (c < SCANCH) renorm_scan(); else renorm_fast();
    }

    // ---- finalize: ll = logaddexp over the two end states ----
    __syncwarp();
    #pragma unroll
    for (int j = 0; j < PSTATES; j++) fin_a[tid * PSTATES + j] = a[j];
    fin_lc[tid] = logacc;
    __syncwarp();
    if (tid == 0) {
        int  sa = 2 * L;
        int  sb = 2 * L - 1;                  // L >= 1 per setup
        float xa = __logf(fmaxf(fin_a[sa], MFLOOR)) + fin_lc[sa / PSTATES];
        float xb = __logf(fmaxf(fin_a[sb], MFLOOR)) + fin_lc[sb / PSTATES];
        float mxx = fmaxf(xa, xb);
        float mnn = fminf(xa, xb);
        float ll  = mxx + __logf(1.0f + __expf(mnn - mxx));
        out[b] = -ll;
    }
}

extern "C" void kernel_launch(void* const* d_in, const int* in_sizes, int n_in,
                              void* d_out, int out_size) {
    const int*   y_true  = (const int*)  d_in[0];   // [B,64] int32
    const float* y_pred  = (const float*)d_in[1];   // [B,1024,256] fp32
    const int*   in_len  = (const int*)  d_in[2];   // [B,1] int32
    const int*   lab_len = (const int*)  d_in[3];   // [B,1] int32
    float*       out     = (float*)      d_out;     // [B,1] fp32

    cudaFuncSetAttribute(ctc_loss_kernel,
                         cudaFuncAttributeMaxDynamicSharedMemorySize,
                         RING_BYTES);

    const int B = out_size;                          // 128
    ctc_loss_kernel<<<B, 32, RING_BYTES>>>(y_true, y_pred, in_len, lab_len, out);
}